// round 16
// baseline (speedup 1.0000x reference)
#include <cuda_runtime.h>
#include <cstdint>
#include <cstddef>

// Fixed problem shapes
#define MROWS  8192           // B*S
#define INDIM  4096
#define OUTDIM 4096
#define RANK   8
#define NTHR   256            // 8 warps per CTA, 2 CTAs per SM (reg-capped)
#define TROWS  32             // rows per tile; warp owns 4 rows
#define NTILE  (MROWS/TROWS)  // 256
#define NC     32             // i-chunks of 128 floats (lane owns 4 i per chunk)

__constant__ float c_nf4[16] = {
    -1.0f, -0.6961928009986877f, -0.5250730514526367f, -0.39491748809814453f,
    -0.28444138169288635f, -0.18477343022823334f, -0.09105003625154495f, 0.0f,
    0.07958029955625534f, 0.16093020141124725f, 0.24611230194568634f,
    0.33791524171829224f, 0.44070982933044434f, 0.5626170039176941f,
    0.7229568362236328f, 1.0f};

// Pre-dequantized W_A (scratch __device__ global; L1/L2-resident, 128 KB)
__device__ __align__(16) float g_WA[RANK * INDIM];    // [r][i]

// W_A-only dequant: 8192 threads x 4 elements (int4), one absmax block each
__global__ void dequantA_kernel(const int* __restrict__ codesA,
                                const float* __restrict__ absmaxA) {
    int i = blockIdx.x * blockDim.x + threadIdx.x;   // 0..8191
    int4 c = ((const int4*)codesA)[i];
    float am = __ldg(absmaxA + (i >> 4));            // elem 4i -> block (4i)>>6
    float4 w = make_float4(c_nf4[c.x & 15] * am, c_nf4[c.y & 15] * am,
                           c_nf4[c.z & 15] * am, c_nf4[c.w & 15] * am);
    ((float4*)g_WA)[i] = w;
}

__device__ __forceinline__ void fma2(unsigned long long& d,
                                     unsigned long long a, unsigned long long b) {
    asm("fma.rn.f32x2 %0, %1, %2, %0;" : "+l"(d) : "l"(a), "l"(b));
}
__device__ __forceinline__ unsigned long long pk2(float v) {
    unsigned long long r; asm("mov.b64 %0, {%1, %1};" : "=l"(r) : "f"(v)); return r;
}
__device__ __forceinline__ unsigned long long pkab(float a, float b) {
    unsigned long long r; asm("mov.b64 %0, {%1, %2};" : "=l"(r) : "f"(a), "f"(b)); return r;
}
__device__ __forceinline__ float2 unpk(unsigned long long v) {
    float2 f; asm("mov.b64 {%0, %1}, %2;" : "=f"(f.x), "=f"(f.y) : "l"(v)); return f;
}
// 16B streaming load (evict-first: protect L1/L2 for weights + codes)
__device__ __forceinline__ ulonglong2 ldcs16(const void* p) {
    ulonglong2 v;
    asm volatile("ld.global.cs.v2.u64 {%0, %1}, [%2];"
                 : "=l"(v.x), "=l"(v.y) : "l"(p));
    return v;
}
// 16B read-only cached load
__device__ __forceinline__ ulonglong2 ldg16(const void* p) {
    ulonglong2 v;
    asm volatile("ld.global.nc.v2.u64 {%0, %1}, [%2];"
                 : "=l"(v.x), "=l"(v.y) : "l"(p));
    return v;
}
// 16B streaming store (evict-first: output is dead-on-arrival for L2)
__device__ __forceinline__ void stcs16(void* p, ulonglong2 v) {
    asm volatile("st.global.cs.v2.u64 [%0], {%1, %2};"
                 :: "l"(p), "l"(v.x), "l"(v.y) : "memory");
}

__global__ void __launch_bounds__(NTHR, 2)
qlora_kernel(const float* __restrict__ x,
             const int* __restrict__ codesB, const float* __restrict__ absmaxB,
             float* __restrict__ out)
{
    __shared__ float sInt[TROWS * RANK];   // interm[row][r]
    __shared__ float sNF[16 * 32];         // NF4 table, 32 bank-replicated copies
    const int tid = threadIdx.x, lane = tid & 31, wid = tid >> 5;
    const int tile = blockIdx.x;

    // bank-replicated NF4 table: copy for lane l lives at [idx*32 + l]
    #pragma unroll
    for (int k = tid; k < 512; k += NTHR) sNF[k] = c_nf4[k >> 5];

    // ---- phase 1 (R13-proven): warp owns rows 4*wid..+3; lane owns 16B/chunk ----
    const char* xr0 = (const char*)(x + ((size_t)tile * TROWS + wid * 4) * INDIM
                                      + 4 * lane);
    const char* xr1 = xr0 + INDIM * 4;
    const char* xr2 = xr1 + INDIM * 4;
    const char* xr3 = xr2 + INDIM * 4;

    unsigned long long acc[4][RANK];
    #pragma unroll
    for (int m = 0; m < 4; m++)
        #pragma unroll
        for (int r = 0; r < RANK; r++) acc[m][r] = 0ull;

    const ulonglong2* __restrict__ wa = (const ulonglong2*)g_WA;  // [r][i/4]
    const int wl = lane;

    ulonglong2 xa[4], xb[4];
    xa[0] = ldcs16(xr0); xa[1] = ldcs16(xr1);
    xa[2] = ldcs16(xr2); xa[3] = ldcs16(xr3);

    #pragma unroll 1
    for (int c = 0; c < NC; c += 2) {
        {
            int off = (c + 1) * 512;
            xb[0] = ldcs16(xr0 + off); xb[1] = ldcs16(xr1 + off);
            xb[2] = ldcs16(xr2 + off); xb[3] = ldcs16(xr3 + off);
        }
        #pragma unroll
        for (int r = 0; r < RANK; r++) {
            ulonglong2 wv = ldg16(wa + (size_t)r * (INDIM / 4) + c * 32 + wl);
            #pragma unroll
            for (int m = 0; m < 4; m++) {
                fma2(acc[m][r], xa[m].x, wv.x);
                fma2(acc[m][r], xa[m].y, wv.y);
            }
        }
        if (c + 2 < NC) {
            int off = (c + 2) * 512;
            xa[0] = ldcs16(xr0 + off); xa[1] = ldcs16(xr1 + off);
            xa[2] = ldcs16(xr2 + off); xa[3] = ldcs16(xr3 + off);
        }
        #pragma unroll
        for (int r = 0; r < RANK; r++) {
            ulonglong2 wv = ldg16(wa + (size_t)r * (INDIM / 4) + (c + 1) * 32 + wl);
            #pragma unroll
            for (int m = 0; m < 4; m++) {
                fma2(acc[m][r], xb[m].x, wv.x);
                fma2(acc[m][r], xb[m].y, wv.y);
            }
        }
    }

    // ---- warp-local reduction: horizontal add + butterfly over 32 lanes ----
    #pragma unroll
    for (int m = 0; m < 4; m++) {
        float v[RANK];
        #pragma unroll
        for (int r = 0; r < RANK; r++) {
            float2 p = unpk(acc[m][r]);
            float s = p.x + p.y;
            s += __shfl_xor_sync(0xffffffffu, s, 16);
            s += __shfl_xor_sync(0xffffffffu, s, 8);
            s += __shfl_xor_sync(0xffffffffu, s, 4);
            s += __shfl_xor_sync(0xffffffffu, s, 2);
            s += __shfl_xor_sync(0xffffffffu, s, 1);
            v[r] = s;
        }
        if (lane == 0) {
            float4* dst = (float4*)(sInt + (wid * 4 + m) * RANK);
            dst[0] = make_float4(v[0], v[1], v[2], v[3]);
            dst[1] = make_float4(v[4], v[5], v[6], v[7]);
        }
    }
    __syncthreads();   // publishes sInt AND sNF

    // ---- phase 2 epilogue: W_B dequantized in-place from codes ----
    {
        size_t outbase = (size_t)tile * TROWS * OUTDIM;
        #pragma unroll
        for (int og = 0; og < 4; og++) {
            int g = tid + og * NTHR;                       // float4 col group
            float am = 4.0f * __ldg(absmaxB + (g >> 1));   // cols 4g..4g+3 share
            int cc[32];
            const int4* cbp = (const int4*)codesB + g * 8; // rows o=4g..4g+3 x 8r
            #pragma unroll
            for (int q2 = 0; q2 < 8; q2++) ((int4*)cc)[q2] = __ldg(cbp + q2);
            unsigned long long wb01[RANK], wb23[RANK];
            #pragma unroll
            for (int r = 0; r < RANK; r++) {
                float w0 = sNF[(cc[r]      & 15) * 32 + lane] * am;
                float w1 = sNF[(cc[8 + r]  & 15) * 32 + lane] * am;
                float w2 = sNF[(cc[16 + r] & 15) * 32 + lane] * am;
                float w3 = sNF[(cc[24 + r] & 15) * 32 + lane] * am;
                wb01[r] = pkab(w0, w1);
                wb23[r] = pkab(w2, w3);
            }
            #pragma unroll 4
            for (int m = 0; m < TROWS; m++) {
                const float4* ip = (const float4*)sInt + m * 2;
                float4 s0 = ip[0], s1 = ip[1];   // broadcast LDS
                float sv[RANK] = { s0.x, s0.y, s0.z, s0.w,
                                   s1.x, s1.y, s1.z, s1.w };
                unsigned long long o01 = 0ull, o23 = 0ull;
                #pragma unroll
                for (int r = 0; r < RANK; r++) {
                    unsigned long long s2 = pk2(sv[r]);
                    fma2(o01, s2, wb01[r]);
                    fma2(o23, s2, wb23[r]);
                }
                ulonglong2 ov; ov.x = o01; ov.y = o23;
                stcs16(out + outbase + (size_t)m * OUTDIM + g * 4, ov);
            }
        }
    }
}

extern "C" void kernel_launch(void* const* d_in, const int* in_sizes, int n_in,
                              void* d_out, int out_size) {
    const float* x        = (const float*)d_in[0];
    const int*   codes_A  = (const int*)d_in[1];
    const float* absmax_A = (const float*)d_in[2];
    const int*   codes_B  = (const int*)d_in[3];
    const float* absmax_B = (const float*)d_in[4];
    float*       out      = (float*)d_out;
    (void)in_sizes; (void)n_in; (void)out_size;

    // W_A-only dequant: 8192 threads, 4 elems each (vectorized)
    dequantA_kernel<<<32, 256>>>(codes_A, absmax_A);

    // one CTA per 32-row tile; 2 CTAs co-resident per SM; one wave
    qlora_kernel<<<NTILE, NTHR>>>(x, codes_B, absmax_B, out);
}

// round 17
// speedup vs baseline: 1.1679x; 1.1679x over previous
#include <cuda_runtime.h>
#include <cstdint>
#include <cstddef>

// Fixed problem shapes
#define MROWS  8192           // B*S
#define INDIM  4096
#define OUTDIM 4096
#define RANK   8
#define NTHR   256            // 8 warps per CTA, 2 CTAs per SM (reg-capped)
#define TROWS  32             // rows per tile; warp owns 4 rows
#define NTILE  (MROWS/TROWS)  // 256
#define NC     32             // i-chunks of 128 floats (lane owns 4 i per chunk)

__constant__ float c_nf4[16] = {
    -1.0f, -0.6961928009986877f, -0.5250730514526367f, -0.39491748809814453f,
    -0.28444138169288635f, -0.18477343022823334f, -0.09105003625154495f, 0.0f,
    0.07958029955625534f, 0.16093020141124725f, 0.24611230194568634f,
    0.33791524171829224f, 0.44070982933044434f, 0.5626170039176941f,
    0.7229568362236328f, 1.0f};

// Pre-dequantized weights (scratch __device__ globals; L1/L2-resident)
__device__ __align__(16) float g_WA[RANK * INDIM];    // [r][i]
__device__ __align__(16) float g_WBt[RANK * OUTDIM];  // [r][o], pre-scaled by 4.0

// Merged vectorized dequant: thread i handles 4 consecutive codes (int4).
// i in [0, 8192): W_A elems 4i..4i+3 (one absmax block: (4i)>>6 = i>>4).
// i in [8192, 16384): W_B codes j=4(i-8192)..+3 — all share o=j>>3, block j>>6.
__global__ void dequant_kernel(const int* __restrict__ codesA,
                               const float* __restrict__ absmaxA,
                               const int* __restrict__ codesB,
                               const float* __restrict__ absmaxB) {
    int i = blockIdx.x * blockDim.x + threadIdx.x;
    if (i < 8192) {
        int4 c = ((const int4*)codesA)[i];
        float am = __ldg(absmaxA + (i >> 4));
        float4 w = make_float4(c_nf4[c.x & 15] * am, c_nf4[c.y & 15] * am,
                               c_nf4[c.z & 15] * am, c_nf4[c.w & 15] * am);
        ((float4*)g_WA)[i] = w;
    } else {
        int ib = i - 8192;                     // 0..8191
        int4 c = ((const int4*)codesB)[ib];
        int j0 = ib * 4;
        int o = j0 >> 3;                       // same for all 4 codes
        int rb = j0 & 7;                       // 0 or 4
        float am = 4.0f * __ldg(absmaxB + (j0 >> 6));
        g_WBt[(rb + 0) * OUTDIM + o] = c_nf4[c.x & 15] * am;
        g_WBt[(rb + 1) * OUTDIM + o] = c_nf4[c.y & 15] * am;
        g_WBt[(rb + 2) * OUTDIM + o] = c_nf4[c.z & 15] * am;
        g_WBt[(rb + 3) * OUTDIM + o] = c_nf4[c.w & 15] * am;
    }
}

__device__ __forceinline__ void fma2(unsigned long long& d,
                                     unsigned long long a, unsigned long long b) {
    asm("fma.rn.f32x2 %0, %1, %2, %0;" : "+l"(d) : "l"(a), "l"(b));
}
__device__ __forceinline__ unsigned long long pk2(float v) {
    unsigned long long r; asm("mov.b64 %0, {%1, %1};" : "=l"(r) : "f"(v)); return r;
}
__device__ __forceinline__ unsigned long long pkab(float a, float b) {
    unsigned long long r; asm("mov.b64 %0, {%1, %2};" : "=l"(r) : "f"(a), "f"(b)); return r;
}
__device__ __forceinline__ float2 unpk(unsigned long long v) {
    float2 f; asm("mov.b64 {%0, %1}, %2;" : "=f"(f.x), "=f"(f.y) : "l"(v)); return f;
}
// 16B streaming load (evict-first: protect L1/L2 for weights)
__device__ __forceinline__ ulonglong2 ldcs16(const void* p) {
    ulonglong2 v;
    asm volatile("ld.global.cs.v2.u64 {%0, %1}, [%2];"
                 : "=l"(v.x), "=l"(v.y) : "l"(p));
    return v;
}
// 16B read-only cached load
__device__ __forceinline__ ulonglong2 ldg16(const void* p) {
    ulonglong2 v;
    asm volatile("ld.global.nc.v2.u64 {%0, %1}, [%2];"
                 : "=l"(v.x), "=l"(v.y) : "l"(p));
    return v;
}

__global__ void __launch_bounds__(NTHR, 2)
qlora_kernel(const float* __restrict__ x, float* __restrict__ out)
{
    __shared__ float sInt[TROWS * RANK];   // interm[row][r]
    const int tid = threadIdx.x, lane = tid & 31, wid = tid >> 5;
    const int tile = blockIdx.x;

    // ---- phase 1: warp owns rows 4*wid..+3; lane owns i = 4*lane + 128*c ----
    const char* xr0 = (const char*)(x + ((size_t)tile * TROWS + wid * 4) * INDIM
                                      + 4 * lane);
    const char* xr1 = xr0 + INDIM * 4;
    const char* xr2 = xr1 + INDIM * 4;
    const char* xr3 = xr2 + INDIM * 4;

    unsigned long long acc[4][RANK];
    #pragma unroll
    for (int m = 0; m < 4; m++)
        #pragma unroll
        for (int r = 0; r < RANK; r++) acc[m][r] = 0ull;

    const ulonglong2* __restrict__ wa = (const ulonglong2*)g_WA;  // [r][i/4]
    const int wl = lane;

    ulonglong2 xa[4], xb[4];
    xa[0] = ldcs16(xr0); xa[1] = ldcs16(xr1);
    xa[2] = ldcs16(xr2); xa[3] = ldcs16(xr3);

    #pragma unroll 1
    for (int c = 0; c < NC; c += 2) {
        // prefetch chunk c+1 (always valid: c <= 30)
        {
            int off = (c + 1) * 512;   // 128 floats = 512 B
            xb[0] = ldcs16(xr0 + off); xb[1] = ldcs16(xr1 + off);
            xb[2] = ldcs16(xr2 + off); xb[3] = ldcs16(xr3 + off);
        }
        // compute chunk c with xa
        #pragma unroll
        for (int r = 0; r < RANK; r++) {
            ulonglong2 wv = ldg16(wa + (size_t)r * (INDIM / 4) + c * 32 + wl);
            #pragma unroll
            for (int m = 0; m < 4; m++) {
                fma2(acc[m][r], xa[m].x, wv.x);
                fma2(acc[m][r], xa[m].y, wv.y);
            }
        }
        // prefetch chunk c+2 into xa (guarded at the tail)
        if (c + 2 < NC) {
            int off = (c + 2) * 512;
            xa[0] = ldcs16(xr0 + off); xa[1] = ldcs16(xr1 + off);
            xa[2] = ldcs16(xr2 + off); xa[3] = ldcs16(xr3 + off);
        }
        // compute chunk c+1 with xb
        #pragma unroll
        for (int r = 0; r < RANK; r++) {
            ulonglong2 wv = ldg16(wa + (size_t)r * (INDIM / 4) + (c + 1) * 32 + wl);
            #pragma unroll
            for (int m = 0; m < 4; m++) {
                fma2(acc[m][r], xb[m].x, wv.x);
                fma2(acc[m][r], xb[m].y, wv.y);
            }
        }
    }

    // ---- warp-local reduction: horizontal add + butterfly over 32 lanes ----
    #pragma unroll
    for (int m = 0; m < 4; m++) {
        float v[RANK];
        #pragma unroll
        for (int r = 0; r < RANK; r++) {
            float2 p = unpk(acc[m][r]);
            float s = p.x + p.y;
            s += __shfl_xor_sync(0xffffffffu, s, 16);
            s += __shfl_xor_sync(0xffffffffu, s, 8);
            s += __shfl_xor_sync(0xffffffffu, s, 4);
            s += __shfl_xor_sync(0xffffffffu, s, 2);
            s += __shfl_xor_sync(0xffffffffu, s, 1);
            v[r] = s;
        }
        if (lane == 0) {
            float4* dst = (float4*)(sInt + (wid * 4 + m) * RANK);
            dst[0] = make_float4(v[0], v[1], v[2], v[3]);
            dst[1] = make_float4(v[4], v[5], v[6], v[7]);
        }
    }
    __syncthreads();

    // ---- phase 2 epilogue: thread owns 4 float4 col groups ----
    {
        size_t outbase = (size_t)tile * TROWS * OUTDIM;
        const float4* gWB4 = (const float4*)g_WBt;
        #pragma unroll
        for (int og = 0; og < 4; og++) {
            int g = tid + og * NTHR;
            unsigned long long wb01[RANK], wb23[RANK];
            #pragma unroll
            for (int r = 0; r < RANK; r++) {
                float4 w = __ldg(gWB4 + r * (OUTDIM / 4) + g);
                wb01[r] = pkab(w.x, w.y);
                wb23[r] = pkab(w.z, w.w);
            }
            #pragma unroll 4
            for (int m = 0; m < TROWS; m++) {
                const float4* ip = (const float4*)sInt + m * 2;
                float4 s0 = ip[0], s1 = ip[1];   // broadcast LDS
                float sv[RANK] = { s0.x, s0.y, s0.z, s0.w,
                                   s1.x, s1.y, s1.z, s1.w };
                unsigned long long o01 = 0ull, o23 = 0ull;
                #pragma unroll
                for (int r = 0; r < RANK; r++) {
                    unsigned long long s2 = pk2(sv[r]);
                    fma2(o01, s2, wb01[r]);
                    fma2(o23, s2, wb23[r]);
                }
                ulonglong2 ov; ov.x = o01; ov.y = o23;
                *(ulonglong2*)(out + outbase + (size_t)m * OUTDIM + g * 4) = ov;
            }
        }
    }
}

extern "C" void kernel_launch(void* const* d_in, const int* in_sizes, int n_in,
                              void* d_out, int out_size) {
    const float* x        = (const float*)d_in[0];
    const int*   codes_A  = (const int*)d_in[1];
    const float* absmax_A = (const float*)d_in[2];
    const int*   codes_B  = (const int*)d_in[3];
    const float* absmax_B = (const float*)d_in[4];
    float*       out      = (float*)d_out;
    (void)in_sizes; (void)n_in; (void)out_size;

    // single merged vectorized dequant: 16384 threads, 4 codes each
    dequant_kernel<<<64, 256>>>(codes_A, absmax_A, codes_B, absmax_B);

    // one CTA per 32-row tile; 2 CTAs co-resident per SM; one wave
    qlora_kernel<<<NTILE, NTHR>>>(x, out);
}